// round 2
// baseline (speedup 1.0000x reference)
#include <cuda_runtime.h>
#include <cstdint>

#define BB 16
#define TT 512
#define NB 16
#define CH 8

// ---------------- scratch (static device arrays; no allocation) ----------------
__device__ float g_q[BB*NB*2*TT*2];    // [b][n][h][t][d] pre-scaled by 1/sqrt(2)
__device__ float g_k[BB*NB*2*TT*2];
__device__ float g_v[BB*NB*2*TT*2];
__device__ float g_o[BB*NB*2*TT*2];    // block attn output
__device__ float g_ab[BB*TT*64];       // all_blocks
__device__ float g_cq[BB*CH*TT*8];     // pre-scaled by 1/sqrt(8)
__device__ float g_ck[BB*CH*TT*8];
__device__ float g_cv[BB*CH*TT*8];
__device__ float g_co[BB*TT*64];       // cross attn output (normalized)
__device__ float g_linv[BB*CH*TT];     // 1/sum_exp per (b,h,t)
__device__ float g_entp[BB*TT*8];      // partial entropy sums per s-chunk
__device__ float g_probs[(size_t)BB*CH*TT*TT];  // [b][h][s][t] unnormalized exp

__device__ __forceinline__ float gelu_f(float x){
    return 0.5f * x * (1.0f + erff(x * 0.70710678118654752f));
}

// ---------------- K1: per-token block extraction + tiny QKV ----------------
__global__ void k1_blockqkv(const float* __restrict__ M,
                            const float* __restrict__ w,
                            const float* __restrict__ bias){
    int bt = blockIdx.x;               // B*T
    __shared__ float mrow[64];
    int tid = threadIdx.x;             // 192 = 16 blocks * 12 outputs
    if (tid < 64) mrow[tid] = M[bt*64 + tid];
    __syncthreads();
    int n = tid / 12, e = tid - n*12;
    int br = n >> 2, bc = n & 3;
    int base = 16*br + 2*bc;
    float x0 = mrow[base], x1 = mrow[base+1], x2 = mrow[base+8], x3 = mrow[base+9];
    const float* wp = w + tid*4;       // (n*12+e)*4
    float val = bias[tid] + wp[0]*x0 + wp[1]*x1 + wp[2]*x2 + wp[3]*x3;
    int b = bt >> 9, t = bt & 511;
    if (e < 4){
        int h = e >> 1, d = e & 1;
        g_q[(((b*NB+n)*2+h)*TT + t)*2 + d] = val * 0.70710678118654752f;
    } else if (e < 8){
        int ee = e - 4; int h = ee >> 1, d = ee & 1;
        g_k[(((b*NB+n)*2+h)*TT + t)*2 + d] = val;
    } else {
        int ee = e - 8; int h = ee >> 1, d = ee & 1;
        g_v[(((b*NB+n)*2+h)*TT + t)*2 + d] = val;
    }
}

// ---------------- K2: 512 tiny attentions (d=2) ----------------
__global__ void __launch_bounds__(TT) k2_blockattn(){
    int c = blockIdx.x;                // B*NB*2 = 512
    int base = c * TT * 2;
    __shared__ float2 sK[TT];
    __shared__ float2 sV[TT];
    int t = threadIdx.x;
    sK[t] = ((const float2*)(g_k + base))[t];
    sV[t] = ((const float2*)(g_v + base))[t];
    __syncthreads();
    float2 q = ((const float2*)(g_q + base))[t];
    float l = 0.f, o0 = 0.f, o1 = 0.f;
    #pragma unroll 8
    for (int s = 0; s < TT; s++){
        float sc = fmaf(q.x, sK[s].x, q.y * sK[s].y);
        float p  = __expf(sc);          // scores bounded by data distribution; shift-free softmax
        l += p;
        o0 = fmaf(p, sV[s].x, o0);
        o1 = fmaf(p, sV[s].y, o1);
    }
    float inv = __fdividef(1.f, l);
    ((float2*)(g_o + base))[t] = make_float2(o0*inv, o1*inv);
}

// ---------------- K3: block out-proj -> all_blocks ----------------
__global__ void k3_blockout(const float* __restrict__ w,
                            const float* __restrict__ bias){
    int bt = blockIdx.x; int tid = threadIdx.x;   // 64 = n*4+e
    int b = bt >> 9, t = bt & 511;
    int n = tid >> 2;
    float acc = bias[tid];
    const float* wp = w + tid*4;
    #pragma unroll
    for (int d = 0; d < 4; d++){
        int h = d >> 1, dd = d & 1;
        float od = g_o[(((b*NB+n)*2+h)*TT + t)*2 + dd];
        acc = fmaf(wp[d], od, acc);
    }
    g_ab[bt*64 + tid] = acc;
}

// ---------------- K4: cross QKV projection ----------------
__global__ void k4_crossqkv(const float* __restrict__ w,
                            const float* __restrict__ bias){
    int bt = blockIdx.x; int tid = threadIdx.x;   // 192
    __shared__ float x[64];
    if (tid < 64) x[tid] = g_ab[bt*64 + tid];
    __syncthreads();
    float acc = bias[tid];
    const float* wp = w + tid*64;
    #pragma unroll 16
    for (int j = 0; j < 64; j++) acc = fmaf(wp[j], x[j], acc);
    int b = bt >> 9, t = bt & 511;
    if (tid < 64){
        int h = tid >> 3, d = tid & 7;
        g_cq[((b*CH+h)*TT + t)*8 + d] = acc * 0.35355339059327376f;
    } else if (tid < 128){
        int i = tid - 64; int h = i >> 3, d = i & 7;
        g_ck[((b*CH+h)*TT + t)*8 + d] = acc;
    } else {
        int i = tid - 128; int h = i >> 3, d = i & 7;
        g_cv[((b*CH+h)*TT + t)*8 + d] = acc;
    }
}

// ---------------- K5: cross attention (d=8), store probs for entropy ----------------
__global__ void __launch_bounds__(TT) k5_crossattn(){
    int c = blockIdx.x;                // B*CH = 128
    __shared__ float sK[TT*9];         // padded stride 9 to ease store conflicts
    __shared__ float sV[TT*9];
    int t = threadIdx.x;
    {
        const float4* kp = (const float4*)(g_ck + c*TT*8);
        const float4* vp = (const float4*)(g_cv + c*TT*8);
        float4 ka = kp[t*2], kb = kp[t*2+1];
        float4 va = vp[t*2], vb = vp[t*2+1];
        float* kd = sK + t*9; float* vd = sV + t*9;
        kd[0]=ka.x; kd[1]=ka.y; kd[2]=ka.z; kd[3]=ka.w;
        kd[4]=kb.x; kd[5]=kb.y; kd[6]=kb.z; kd[7]=kb.w;
        vd[0]=va.x; vd[1]=va.y; vd[2]=va.z; vd[3]=va.w;
        vd[4]=vb.x; vd[5]=vb.y; vd[6]=vb.z; vd[7]=vb.w;
    }
    __syncthreads();
    float q[8];
    {
        const float4* qp = (const float4*)(g_cq + c*TT*8);
        float4 qa = qp[t*2], qb = qp[t*2+1];
        q[0]=qa.x; q[1]=qa.y; q[2]=qa.z; q[3]=qa.w;
        q[4]=qb.x; q[5]=qb.y; q[6]=qb.z; q[7]=qb.w;
    }
    float l = 0.f;
    float o[8];
    #pragma unroll
    for (int j = 0; j < 8; j++) o[j] = 0.f;
    float* pr = g_probs + (size_t)c*TT*TT + t;   // [c][s][t] -> coalesced store at fixed s
    #pragma unroll 4
    for (int s = 0; s < TT; s++){
        const float* ks = sK + s*9;
        float sc = q[0]*ks[0];
        #pragma unroll
        for (int j = 1; j < 8; j++) sc = fmaf(q[j], ks[j], sc);
        float p = __expf(sc);
        pr[s*TT] = p;
        l += p;
        const float* vs = sV + s*9;
        #pragma unroll
        for (int j = 0; j < 8; j++) o[j] = fmaf(p, vs[j], o[j]);
    }
    float inv = __fdividef(1.f, l);
    g_linv[c*TT + t] = inv;
    int b = c >> 3, h = c & 7;
    float* cop = g_co + (b*TT + t)*64 + h*8;
    #pragma unroll
    for (int j = 0; j < 8; j++) cop[j] = o[j]*inv;
}

// ---------------- K6: entropy partials (deterministic, no atomics) ----------------
__global__ void __launch_bounds__(128) k6_entropy(){
    int g = blockIdx.x;                // BB*4*8 = 512
    int chunk = g & 7;
    int tile  = (g >> 3) & 3;
    int b     = g >> 5;
    int t = tile*128 + threadIdx.x;
    float invl[8];
    #pragma unroll
    for (int h = 0; h < 8; h++) invl[h] = g_linv[(b*CH+h)*TT + t] * 0.125f;
    float acc = 0.f;
    int s0 = chunk*64;
    #pragma unroll 4
    for (int s = s0; s < s0+64; s++){
        float pm = 0.f;
        #pragma unroll
        for (int h = 0; h < 8; h++)
            pm = fmaf(g_probs[((size_t)(b*CH+h)*TT + s)*TT + t], invl[h], pm);
        acc = fmaf(pm, __logf(pm + 1e-9f), acc);
    }
    g_entp[(b*TT + t)*8 + chunk] = acc;   // entropy = -sum of these
}

// ---------------- reduction helper: stats over 64 values held by tid<64 ----------------
__device__ __forceinline__ float2 blockstats64(float v, int tid, float* s_red){
    float sv = v, sq = v*v;
    #pragma unroll
    for (int o = 16; o > 0; o >>= 1){
        sv += __shfl_down_sync(0xffffffffu, sv, o);
        sq += __shfl_down_sync(0xffffffffu, sq, o);
    }
    if ((tid & 31) == 0){ s_red[(tid>>5)*2] = sv; s_red[(tid>>5)*2+1] = sq; }
    __syncthreads();
    if (tid == 0){
        float S = 0.f, Q = 0.f;
        #pragma unroll
        for (int w = 0; w < 8; w++){ S += s_red[w*2]; Q += s_red[w*2+1]; }
        float mean = S * (1.f/64.f);
        float var  = Q * (1.f/64.f) - mean*mean;
        s_red[0] = mean;
        s_red[1] = rsqrtf(var + 1e-5f);
    }
    __syncthreads();
    float2 r = make_float2(s_red[0], s_red[1]);
    __syncthreads();
    return r;
}

// ---------------- K7: out-proj + LN1 + FFN + LN2 + sensitivity + update ----------------
__global__ void __launch_bounds__(256) k7_fused(
    const float* __restrict__ M, const int* __restrict__ token_ids,
    const float* __restrict__ cwout, const float* __restrict__ cbout,
    const float* __restrict__ g1, const float* __restrict__ be1,
    const float* __restrict__ fw1, const float* __restrict__ fb1,
    const float* __restrict__ fw2, const float* __restrict__ fb2,
    const float* __restrict__ g2, const float* __restrict__ be2,
    const float* __restrict__ sbase, const float* __restrict__ taff,
    const float* __restrict__ sw1, const float* __restrict__ sb1,
    const float* __restrict__ sw2, const float* __restrict__ sb2,
    float* __restrict__ out)
{
    int bt = blockIdx.x;
    int tid = threadIdx.x;
    __shared__ float s_co[64], s_x[64], s_h1[256], s_hs[32], s_sens[16];
    __shared__ float s_red[16];
    __shared__ float s_ent[1];

    if (tid < 64) s_co[tid] = g_co[bt*64 + tid];
    __syncthreads();

    float yv = 0.f;
    if (tid < 64){
        float acc = cbout[tid];
        const float* wp = cwout + tid*64;
        #pragma unroll 8
        for (int j = 0; j < 64; j++) acc = fmaf(wp[j], s_co[j], acc);
        yv = g_ab[bt*64 + tid] + acc;
    }
    float2 st1 = blockstats64(tid < 64 ? yv : 0.f, tid, s_red);
    if (tid < 64) s_x[tid] = (yv - st1.x)*st1.y*g1[tid] + be1[tid];
    __syncthreads();

    // FFN layer 1 (all 256 threads)
    {
        float acc = fb1[tid];
        const float* wp = fw1 + tid*64;
        #pragma unroll 8
        for (int j = 0; j < 64; j++) acc = fmaf(wp[j], s_x[j], acc);
        s_h1[tid] = gelu_f(acc);
    }
    __syncthreads();

    float zv = 0.f;
    if (tid < 64){
        float acc = fb2[tid];
        const float* wp = fw2 + tid*256;
        #pragma unroll 8
        for (int j = 0; j < 256; j++) acc = fmaf(wp[j], s_h1[j], acc);
        zv = s_x[tid] + acc;
    }
    float2 st2 = blockstats64(tid < 64 ? zv : 0.f, tid, s_red);
    if (tid < 64) s_x[tid] = (zv - st2.x)*st2.y*g2[tid] + be2[tid];

    if (tid == 0){
        float e = 0.f;
        #pragma unroll
        for (int c = 0; c < 8; c++) e += g_entp[bt*8 + c];
        s_ent[0] = -e;
    }
    __syncthreads();

    int tok = token_ids[bt];
    if (tid < 32){
        float acc = sb1[tid];
        const float* wp = sw1 + tid*17;
        const float* ap = taff + (size_t)tok*16;
        #pragma unroll
        for (int a = 0; a < 16; a++) acc = fmaf(wp[a], ap[a], acc);
        acc = fmaf(wp[16], s_ent[0], acc);
        s_hs[tid] = gelu_f(acc);
    }
    __syncthreads();
    if (tid < 16){
        float acc = sb2[tid];
        const float* wp = sw2 + tid*32;
        #pragma unroll
        for (int j = 0; j < 32; j++) acc = fmaf(wp[j], s_hs[j], acc);
        s_sens[tid] = sbase[tid] / (1.f + __expf(-acc));
    }
    __syncthreads();
    if (tid < 64){
        float m = M[bt*64 + tid];
        out[bt*64 + tid] = fmaf(s_x[tid] - m, s_sens[tid >> 2], m);
    }
}

// ---------------- launch ----------------
extern "C" void kernel_launch(void* const* d_in, const int* in_sizes, int n_in,
                              void* d_out, int out_size){
    const float* M     = (const float*)d_in[0];
    const int*   tok   = (const int*)  d_in[1];
    const float* bwqkv = (const float*)d_in[2];
    const float* bbqkv = (const float*)d_in[3];
    const float* bwout = (const float*)d_in[4];
    const float* bbout = (const float*)d_in[5];
    const float* cwqkv = (const float*)d_in[6];
    const float* cbqkv = (const float*)d_in[7];
    const float* cwout = (const float*)d_in[8];
    const float* cbout = (const float*)d_in[9];
    const float* g1    = (const float*)d_in[10];
    const float* b1    = (const float*)d_in[11];
    const float* fw1   = (const float*)d_in[12];
    const float* fb1   = (const float*)d_in[13];
    const float* fw2   = (const float*)d_in[14];
    const float* fb2   = (const float*)d_in[15];
    const float* g2    = (const float*)d_in[16];
    const float* b2    = (const float*)d_in[17];
    const float* sbase = (const float*)d_in[18];
    const float* taff  = (const float*)d_in[19];
    const float* sw1   = (const float*)d_in[20];
    const float* sb1   = (const float*)d_in[21];
    const float* sw2   = (const float*)d_in[22];
    const float* sb2   = (const float*)d_in[23];

    k1_blockqkv<<<BB*TT, 192>>>(M, bwqkv, bbqkv);
    k2_blockattn<<<BB*NB*2, TT>>>();
    k3_blockout<<<BB*TT, 64>>>(bwout, bbout);
    k4_crossqkv<<<BB*TT, 192>>>(cwqkv, cbqkv);
    k5_crossattn<<<BB*CH, TT>>>();
    k6_entropy<<<BB*4*8, 128>>>();
    k7_fused<<<BB*TT, 256>>>(M, tok, cwout, cbout, g1, b1, fw1, fb1,
                             fw2, fb2, g2, b2, sbase, taff,
                             sw1, sb1, sw2, sb2, (float*)d_out);
}

// round 3
// speedup vs baseline: 5.7676x; 5.7676x over previous
#include <cuda_runtime.h>
#include <cuda_fp16.h>
#include <cstdint>

#define BB 16
#define TT 512
#define NB 16
#define CH 8

// ---------------- scratch (static device arrays; no allocation) ----------------
__device__ float g_q[BB*NB*2*TT*2];    // [b][n][h][t][d] pre-scaled by 1/sqrt(2)
__device__ float g_k[BB*NB*2*TT*2];
__device__ float g_v[BB*NB*2*TT*2];
__device__ float g_o[BB*NB*2*TT*2];    // block attn output
__device__ float g_ab[BB*TT*64];       // all_blocks
__device__ float g_cq[BB*CH*TT*8];     // pre-scaled by 1/sqrt(8)
__device__ float g_ck[BB*CH*TT*8];
__device__ float g_cv[BB*CH*TT*8];
__device__ float g_co[BB*TT*64];       // cross attn output (normalized)
__device__ float g_linv[BB*CH*TT];     // 1/sum_exp per (b,h,t)
__device__ float g_entp[BB*TT*8];      // partial entropy sums per s-chunk
__device__ __half g_probs[(size_t)BB*CH*TT*TT];  // [b][h][s][t] unnormalized exp (fp16)

// transposed weights: wT[j*O + o] = w[o*J + j]
__device__ float g_cwqkvT[64*192];
__device__ float g_cwoutT[64*64];
__device__ float g_fw1T[64*256];
__device__ float g_fw2T[256*64];

__device__ __forceinline__ float gelu_f(float x){
    return 0.5f * x * (1.0f + erff(x * 0.70710678118654752f));
}

// ---------------- K0: transpose weights (writes coalesced) ----------------
__global__ void k0_transpose(const float* __restrict__ cwqkv,
                             const float* __restrict__ cwout,
                             const float* __restrict__ fw1,
                             const float* __restrict__ fw2){
    int stride = gridDim.x * blockDim.x;
    int tid0 = blockIdx.x * blockDim.x + threadIdx.x;
    for (int idx = tid0; idx < 64*192; idx += stride){
        int j = idx / 192, o = idx - j*192;
        g_cwqkvT[idx] = cwqkv[o*64 + j];
    }
    for (int idx = tid0; idx < 64*64; idx += stride){
        int j = idx >> 6, o = idx & 63;
        g_cwoutT[idx] = cwout[o*64 + j];
    }
    for (int idx = tid0; idx < 64*256; idx += stride){
        int j = idx >> 8, o = idx & 255;
        g_fw1T[idx] = fw1[o*64 + j];
    }
    for (int idx = tid0; idx < 256*64; idx += stride){
        int j = idx >> 6, o = idx & 63;
        g_fw2T[idx] = fw2[o*256 + j];
    }
}

// ---------------- K1: per-token block extraction + tiny QKV ----------------
__global__ void k1_blockqkv(const float* __restrict__ M,
                            const float* __restrict__ w,
                            const float* __restrict__ bias){
    int bt = blockIdx.x;               // B*T
    __shared__ float mrow[64];
    int tid = threadIdx.x;             // 192 = 16 blocks * 12 outputs
    if (tid < 64) mrow[tid] = M[bt*64 + tid];
    __syncthreads();
    int n = tid / 12, e = tid - n*12;
    int br = n >> 2, bc = n & 3;
    int base = 16*br + 2*bc;
    float x0 = mrow[base], x1 = mrow[base+1], x2 = mrow[base+8], x3 = mrow[base+9];
    const float* wp = w + tid*4;       // (n*12+e)*4
    float val = bias[tid] + wp[0]*x0 + wp[1]*x1 + wp[2]*x2 + wp[3]*x3;
    int b = bt >> 9, t = bt & 511;
    if (e < 4){
        int h = e >> 1, d = e & 1;
        g_q[(((b*NB+n)*2+h)*TT + t)*2 + d] = val * 0.70710678118654752f;
    } else if (e < 8){
        int ee = e - 4; int h = ee >> 1, d = ee & 1;
        g_k[(((b*NB+n)*2+h)*TT + t)*2 + d] = val;
    } else {
        int ee = e - 8; int h = ee >> 1, d = ee & 1;
        g_v[(((b*NB+n)*2+h)*TT + t)*2 + d] = val;
    }
}

// ---------------- K2: 512 tiny attentions (d=2) ----------------
__global__ void __launch_bounds__(TT) k2_blockattn(){
    int c = blockIdx.x;                // B*NB*2 = 512
    int base = c * TT * 2;
    __shared__ float2 sK[TT];
    __shared__ float2 sV[TT];
    int t = threadIdx.x;
    sK[t] = ((const float2*)(g_k + base))[t];
    sV[t] = ((const float2*)(g_v + base))[t];
    __syncthreads();
    float2 q = ((const float2*)(g_q + base))[t];
    float l = 0.f, o0 = 0.f, o1 = 0.f;
    #pragma unroll 8
    for (int s = 0; s < TT; s++){
        float sc = fmaf(q.x, sK[s].x, q.y * sK[s].y);
        float p  = __expf(sc);          // shift-free softmax: scores bounded by data distribution
        l += p;
        o0 = fmaf(p, sV[s].x, o0);
        o1 = fmaf(p, sV[s].y, o1);
    }
    float inv = __fdividef(1.f, l);
    ((float2*)(g_o + base))[t] = make_float2(o0*inv, o1*inv);
}

// ---------------- K4: block out-proj + cross QKV (merged, coalesced weights) ----------------
__global__ void __launch_bounds__(192) k4_crossqkv(const float* __restrict__ bw,
                            const float* __restrict__ bb,
                            const float* __restrict__ bias){
    int bt = blockIdx.x; int tid = threadIdx.x;   // 192
    int b = bt >> 9, t = bt & 511;
    __shared__ float x[64];
    if (tid < 64){
        // block out-projection: tid = n*4+e
        int n = tid >> 2;
        float acc = bb[tid];
        const float* wp = bw + tid*4;
        #pragma unroll
        for (int d = 0; d < 4; d++){
            int h = d >> 1, dd = d & 1;
            float od = g_o[(((b*NB+n)*2+h)*TT + t)*2 + dd];
            acc = fmaf(wp[d], od, acc);
        }
        x[tid] = acc;
        g_ab[bt*64 + tid] = acc;
    }
    __syncthreads();
    float acc = bias[tid];
    #pragma unroll 16
    for (int j = 0; j < 64; j++) acc = fmaf(g_cwqkvT[j*192 + tid], x[j], acc);
    if (tid < 64){
        int h = tid >> 3, d = tid & 7;
        g_cq[((b*CH+h)*TT + t)*8 + d] = acc * 0.35355339059327376f;
    } else if (tid < 128){
        int i = tid - 64; int h = i >> 3, d = i & 7;
        g_ck[((b*CH+h)*TT + t)*8 + d] = acc;
    } else {
        int i = tid - 128; int h = i >> 3, d = i & 7;
        g_cv[((b*CH+h)*TT + t)*8 + d] = acc;
    }
}

// ---------------- K5: cross attention (d=8), store fp16 probs for entropy ----------------
__global__ void __launch_bounds__(TT) k5_crossattn(){
    int c = blockIdx.x;                // B*CH = 128
    __shared__ float sK[TT*9];         // padded stride 9
    __shared__ float sV[TT*9];
    int t = threadIdx.x;
    {
        const float4* kp = (const float4*)(g_ck + c*TT*8);
        const float4* vp = (const float4*)(g_cv + c*TT*8);
        float4 ka = kp[t*2], kb = kp[t*2+1];
        float4 va = vp[t*2], vb = vp[t*2+1];
        float* kd = sK + t*9; float* vd = sV + t*9;
        kd[0]=ka.x; kd[1]=ka.y; kd[2]=ka.z; kd[3]=ka.w;
        kd[4]=kb.x; kd[5]=kb.y; kd[6]=kb.z; kd[7]=kb.w;
        vd[0]=va.x; vd[1]=va.y; vd[2]=va.z; vd[3]=va.w;
        vd[4]=vb.x; vd[5]=vb.y; vd[6]=vb.z; vd[7]=vb.w;
    }
    __syncthreads();
    float q[8];
    {
        const float4* qp = (const float4*)(g_cq + c*TT*8);
        float4 qa = qp[t*2], qb = qp[t*2+1];
        q[0]=qa.x; q[1]=qa.y; q[2]=qa.z; q[3]=qa.w;
        q[4]=qb.x; q[5]=qb.y; q[6]=qb.z; q[7]=qb.w;
    }
    float l = 0.f;
    float o[8];
    #pragma unroll
    for (int j = 0; j < 8; j++) o[j] = 0.f;
    __half* pr = g_probs + (size_t)c*TT*TT + t;   // [c][s][t] coalesced in t
    #pragma unroll 4
    for (int s = 0; s < TT; s++){
        const float* ks = sK + s*9;
        float sc = q[0]*ks[0];
        #pragma unroll
        for (int j = 1; j < 8; j++) sc = fmaf(q[j], ks[j], sc);
        float p = __expf(sc);
        pr[s*TT] = __float2half(p);
        l += p;
        const float* vs = sV + s*9;
        #pragma unroll
        for (int j = 0; j < 8; j++) o[j] = fmaf(p, vs[j], o[j]);
    }
    float inv = __fdividef(1.f, l);
    g_linv[c*TT + t] = inv;
    int b = c >> 3, h = c & 7;
    float* cop = g_co + (b*TT + t)*64 + h*8;
    #pragma unroll
    for (int j = 0; j < 8; j++) cop[j] = o[j]*inv;
}

// ---------------- K6: entropy partials (deterministic, no atomics) ----------------
__global__ void __launch_bounds__(128) k6_entropy(){
    int g = blockIdx.x;                // BB*4*8 = 512
    int chunk = g & 7;
    int tile  = (g >> 3) & 3;
    int b     = g >> 5;
    int t = tile*128 + threadIdx.x;
    float invl[8];
    #pragma unroll
    for (int h = 0; h < 8; h++) invl[h] = g_linv[(b*CH+h)*TT + t] * 0.125f;
    float acc = 0.f;
    int s0 = chunk*64;
    #pragma unroll 4
    for (int s = s0; s < s0+64; s++){
        float pm = 0.f;
        #pragma unroll
        for (int h = 0; h < 8; h++)
            pm = fmaf(__half2float(g_probs[((size_t)(b*CH+h)*TT + s)*TT + t]), invl[h], pm);
        acc = fmaf(pm, __logf(pm + 1e-9f), acc);
    }
    g_entp[(b*TT + t)*8 + chunk] = acc;   // entropy = -sum of these
}

// ---------------- reduction helper: stats over 64 values held by tid<64 ----------------
__device__ __forceinline__ float2 blockstats64(float v, int tid, float* s_red){
    float sv = v, sq = v*v;
    #pragma unroll
    for (int o = 16; o > 0; o >>= 1){
        sv += __shfl_down_sync(0xffffffffu, sv, o);
        sq += __shfl_down_sync(0xffffffffu, sq, o);
    }
    if ((tid & 31) == 0){ s_red[(tid>>5)*2] = sv; s_red[(tid>>5)*2+1] = sq; }
    __syncthreads();
    if (tid == 0){
        float S = 0.f, Q = 0.f;
        #pragma unroll
        for (int w = 0; w < 8; w++){ S += s_red[w*2]; Q += s_red[w*2+1]; }
        float mean = S * (1.f/64.f);
        float var  = Q * (1.f/64.f) - mean*mean;
        s_red[0] = mean;
        s_red[1] = rsqrtf(var + 1e-5f);
    }
    __syncthreads();
    float2 r = make_float2(s_red[0], s_red[1]);
    __syncthreads();
    return r;
}

// ---------------- K7: out-proj + LN1 + FFN + LN2 + sensitivity + update ----------------
__global__ void __launch_bounds__(256) k7_fused(
    const float* __restrict__ M, const int* __restrict__ token_ids,
    const float* __restrict__ cbout,
    const float* __restrict__ g1, const float* __restrict__ be1,
    const float* __restrict__ fb1,
    const float* __restrict__ fb2,
    const float* __restrict__ g2, const float* __restrict__ be2,
    const float* __restrict__ sbase, const float* __restrict__ taff,
    const float* __restrict__ sw1, const float* __restrict__ sb1,
    const float* __restrict__ sw2, const float* __restrict__ sb2,
    float* __restrict__ out)
{
    int bt = blockIdx.x;
    int tid = threadIdx.x;
    __shared__ float s_co[64], s_x[64], s_h1[256], s_hs[32], s_sens[16];
    __shared__ float s_part[4][64];
    __shared__ float s_red[16];
    __shared__ float s_ent[1];

    if (tid < 64) s_co[tid] = g_co[bt*64 + tid];
    __syncthreads();

    float yv = 0.f;
    if (tid < 64){
        float acc = cbout[tid];
        #pragma unroll 8
        for (int j = 0; j < 64; j++) acc = fmaf(g_cwoutT[j*64 + tid], s_co[j], acc);
        yv = g_ab[bt*64 + tid] + acc;
    }
    float2 st1 = blockstats64(tid < 64 ? yv : 0.f, tid, s_red);
    if (tid < 64) s_x[tid] = (yv - st1.x)*st1.y*g1[tid] + be1[tid];
    __syncthreads();

    // FFN layer 1 (all 256 threads, coalesced transposed weights)
    {
        float acc = fb1[tid];
        #pragma unroll 8
        for (int j = 0; j < 64; j++) acc = fmaf(g_fw1T[j*256 + tid], s_x[j], acc);
        s_h1[tid] = gelu_f(acc);
    }
    __syncthreads();

    // FFN layer 2: split inner 256 across 4 thread groups, reduce in smem
    {
        int o = tid & 63, qtr = tid >> 6;
        float acc = 0.f;
        int j0 = qtr*64;
        #pragma unroll 8
        for (int j = j0; j < j0+64; j++) acc = fmaf(g_fw2T[j*64 + o], s_h1[j], acc);
        s_part[qtr][o] = acc;
    }
    __syncthreads();

    float zv = 0.f;
    if (tid < 64){
        zv = s_x[tid] + fb2[tid] + s_part[0][tid] + s_part[1][tid] + s_part[2][tid] + s_part[3][tid];
    }
    float2 st2 = blockstats64(tid < 64 ? zv : 0.f, tid, s_red);
    if (tid < 64) s_x[tid] = (zv - st2.x)*st2.y*g2[tid] + be2[tid];

    if (tid == 0){
        float e = 0.f;
        #pragma unroll
        for (int c = 0; c < 8; c++) e += g_entp[bt*8 + c];
        s_ent[0] = -e;
    }
    __syncthreads();

    int tok = token_ids[bt];
    if (tid < 32){
        float acc = sb1[tid];
        const float* wp = sw1 + tid*17;
        const float* ap = taff + (size_t)tok*16;
        #pragma unroll
        for (int a = 0; a < 16; a++) acc = fmaf(wp[a], ap[a], acc);
        acc = fmaf(wp[16], s_ent[0], acc);
        s_hs[tid] = gelu_f(acc);
    }
    __syncthreads();
    if (tid < 16){
        float acc = sb2[tid];
        const float* wp = sw2 + tid*32;
        #pragma unroll
        for (int j = 0; j < 32; j++) acc = fmaf(wp[j], s_hs[j], acc);
        s_sens[tid] = sbase[tid] / (1.f + __expf(-acc));
    }
    __syncthreads();
    if (tid < 64){
        float m = M[bt*64 + tid];
        out[bt*64 + tid] = fmaf(s_x[tid] - m, s_sens[tid >> 2], m);
    }
}

// ---------------- launch ----------------
extern "C" void kernel_launch(void* const* d_in, const int* in_sizes, int n_in,
                              void* d_out, int out_size){
    const float* M     = (const float*)d_in[0];
    const int*   tok   = (const int*)  d_in[1];
    const float* bwqkv = (const float*)d_in[2];
    const float* bbqkv = (const float*)d_in[3];
    const float* bwout = (const float*)d_in[4];
    const float* bbout = (const float*)d_in[5];
    const float* cwqkv = (const float*)d_in[6];
    const float* cbqkv = (const float*)d_in[7];
    const float* cwout = (const float*)d_in[8];
    const float* cbout = (const float*)d_in[9];
    const float* g1    = (const float*)d_in[10];
    const float* b1    = (const float*)d_in[11];
    const float* fw1   = (const float*)d_in[12];
    const float* fb1   = (const float*)d_in[13];
    const float* fw2   = (const float*)d_in[14];
    const float* fb2   = (const float*)d_in[15];
    const float* g2    = (const float*)d_in[16];
    const float* b2    = (const float*)d_in[17];
    const float* sbase = (const float*)d_in[18];
    const float* taff  = (const float*)d_in[19];
    const float* sw1   = (const float*)d_in[20];
    const float* sb1   = (const float*)d_in[21];
    const float* sw2   = (const float*)d_in[22];
    const float* sb2   = (const float*)d_in[23];

    k0_transpose<<<48, 256>>>(cwqkv, cwout, fw1, fw2);
    k1_blockqkv<<<BB*TT, 192>>>(M, bwqkv, bbqkv);
    k2_blockattn<<<BB*NB*2, TT>>>();
    k4_crossqkv<<<BB*TT, 192>>>(bwout, bbout, cbqkv);
    k5_crossattn<<<BB*CH, TT>>>();
    k6_entropy<<<BB*4*8, 128>>>();
    k7_fused<<<BB*TT, 256>>>(M, tok, cbout, g1, b1, fb1, fb2, g2, b2,
                             sbase, taff, sw1, sb1, sw2, sb2, (float*)d_out);
}

// round 4
// speedup vs baseline: 7.4135x; 1.2854x over previous
#include <cuda_runtime.h>
#include <cstdint>

#define BB 16
#define TT 512
#define NB 16
#define CH 8

// ---------------- scratch (static device arrays; no allocation) ----------------
__device__ float  g_q[BB*NB*2*TT*2];     // [b][n][h][t][d] pre-scaled by 1/sqrt(2)
__device__ float4 g_kv[BB*NB*2*TT];      // (k0,k1,v0,v1) interleaved
__device__ float  g_o[BB*NB*2*TT*2];     // block attn output
__device__ float  g_ab[BB*TT*64];        // all_blocks
__device__ float  g_cq[BB*CH*TT*8];      // pre-scaled by 1/sqrt(8)
__device__ float  g_ck[BB*CH*TT*8];
__device__ float  g_cv[BB*CH*TT*8];
__device__ float  g_co[BB*TT*64];        // cross attn output (normalized)
__device__ float  g_linv[BB*CH*TT];      // 1/sum_exp per (b,h,t)
__device__ float  g_entp[BB*TT*4];       // partial entropy sums (4 s-chunks)

// transposed weights: wT[j*O + o] = w[o*J + j]
__device__ float g_cwqkvT[64*192];
__device__ float g_cwoutT[64*64];
__device__ float g_fw1T[64*256];
__device__ float g_fw2T[256*64];

__device__ __forceinline__ float gelu_f(float x){
    return 0.5f * x * (1.0f + erff(x * 0.70710678118654752f));
}

// ---------------- K0: transpose weights ----------------
__global__ void k0_transpose(const float* __restrict__ cwqkv,
                             const float* __restrict__ cwout,
                             const float* __restrict__ fw1,
                             const float* __restrict__ fw2){
    int stride = gridDim.x * blockDim.x;
    int tid0 = blockIdx.x * blockDim.x + threadIdx.x;
    for (int idx = tid0; idx < 64*192; idx += stride){
        int j = idx / 192, o = idx - j*192;
        g_cwqkvT[idx] = cwqkv[o*64 + j];
    }
    for (int idx = tid0; idx < 64*64; idx += stride){
        int j = idx >> 6, o = idx & 63;
        g_cwoutT[idx] = cwout[o*64 + j];
    }
    for (int idx = tid0; idx < 64*256; idx += stride){
        int j = idx >> 8, o = idx & 255;
        g_fw1T[idx] = fw1[o*64 + j];
    }
    for (int idx = tid0; idx < 256*64; idx += stride){
        int j = idx >> 6, o = idx & 63;
        g_fw2T[idx] = fw2[o*256 + j];
    }
}

// ---------------- K1: block extraction + tiny QKV ----------------
__global__ void k1_blockqkv(const float* __restrict__ M,
                            const float* __restrict__ w,
                            const float* __restrict__ bias){
    int bt = blockIdx.x;
    __shared__ float mrow[64];
    int tid = threadIdx.x;             // 192 = 16 blocks * 12 outputs
    if (tid < 64) mrow[tid] = M[bt*64 + tid];
    __syncthreads();
    int n = tid / 12, e = tid - n*12;
    int br = n >> 2, bc = n & 3;
    int base = 16*br + 2*bc;
    float x0 = mrow[base], x1 = mrow[base+1], x2 = mrow[base+8], x3 = mrow[base+9];
    const float* wp = w + tid*4;
    float val = bias[tid] + wp[0]*x0 + wp[1]*x1 + wp[2]*x2 + wp[3]*x3;
    int b = bt >> 9, t = bt & 511;
    if (e < 4){
        int h = e >> 1, d = e & 1;
        g_q[(((b*NB+n)*2+h)*TT + t)*2 + d] = val * 0.70710678118654752f;
    } else if (e < 8){
        int ee = e - 4; int h = ee >> 1, d = ee & 1;
        ((float*)g_kv)[(((b*NB+n)*2+h)*TT + t)*4 + d] = val;       // k -> .x/.y
    } else {
        int ee = e - 8; int h = ee >> 1, d = ee & 1;
        ((float*)g_kv)[(((b*NB+n)*2+h)*TT + t)*4 + 2 + d] = val;   // v -> .z/.w
    }
}

// ---------------- K2: 512 tiny attentions (d=2) ----------------
__global__ void __launch_bounds__(TT) k2_blockattn(){
    int c = blockIdx.x;                // B*NB*2 = 512
    int base = c * TT;
    __shared__ float4 sKV[TT];
    int t = threadIdx.x;
    sKV[t] = g_kv[base + t];
    __syncthreads();
    float2 q = ((const float2*)g_q)[base + t];
    float l0 = 0.f, l1 = 0.f;
    float oa0 = 0.f, oa1 = 0.f, ob0 = 0.f, ob1 = 0.f;
    #pragma unroll 4
    for (int s = 0; s < TT; s += 2){
        float4 kv0 = sKV[s];
        float4 kv1 = sKV[s+1];
        float p0 = __expf(fmaf(q.x, kv0.x, q.y * kv0.y));  // shift-free softmax
        float p1 = __expf(fmaf(q.x, kv1.x, q.y * kv1.y));
        l0 += p0; l1 += p1;
        oa0 = fmaf(p0, kv0.z, oa0); oa1 = fmaf(p0, kv0.w, oa1);
        ob0 = fmaf(p1, kv1.z, ob0); ob1 = fmaf(p1, kv1.w, ob1);
    }
    float inv = __fdividef(1.f, l0 + l1);
    ((float2*)g_o)[base + t] = make_float2((oa0+ob0)*inv, (oa1+ob1)*inv);
}

// ---------------- K4: block out-proj + cross QKV, 8 tokens/block ----------------
__global__ void __launch_bounds__(192) k4_crossqkv(const float* __restrict__ bw,
                                                   const float* __restrict__ bb,
                                                   const float* __restrict__ bias){
    int bt0 = blockIdx.x * 8;
    int b = bt0 >> 9;
    int tid = threadIdx.x;
    __shared__ float s_xT[64*8];       // x[o][tok]

    for (int idx = tid; idx < 512; idx += 192){
        int tok = idx >> 6, o = idx & 63;
        int t = (bt0 + tok) & 511;
        int n = o >> 2;
        float acc = bb[o];
        const float* wp = bw + o*4;
        #pragma unroll
        for (int d = 0; d < 4; d++){
            int h = d >> 1, dd = d & 1;
            acc = fmaf(wp[d], g_o[(((b*NB+n)*2+h)*TT + t)*2 + dd], acc);
        }
        s_xT[o*8 + tok] = acc;
        g_ab[(bt0+tok)*64 + o] = acc;
    }
    __syncthreads();

    float acc[8];
    float bs = bias[tid];
    #pragma unroll
    for (int k = 0; k < 8; k++) acc[k] = bs;
    #pragma unroll 8
    for (int j = 0; j < 64; j++){
        float w = g_cwqkvT[j*192 + tid];
        float4 x0 = *(const float4*)&s_xT[j*8];
        float4 x1 = *(const float4*)&s_xT[j*8 + 4];
        acc[0] = fmaf(w, x0.x, acc[0]); acc[1] = fmaf(w, x0.y, acc[1]);
        acc[2] = fmaf(w, x0.z, acc[2]); acc[3] = fmaf(w, x0.w, acc[3]);
        acc[4] = fmaf(w, x1.x, acc[4]); acc[5] = fmaf(w, x1.y, acc[5]);
        acc[6] = fmaf(w, x1.z, acc[6]); acc[7] = fmaf(w, x1.w, acc[7]);
    }
    #pragma unroll
    for (int tok = 0; tok < 8; tok++){
        int t = (bt0 + tok) & 511;
        float v = acc[tok];
        if (tid < 64){
            int h = tid >> 3, d = tid & 7;
            g_cq[((b*CH+h)*TT + t)*8 + d] = v * 0.35355339059327376f;
        } else if (tid < 128){
            int i = tid - 64; int h = i >> 3, d = i & 7;
            g_ck[((b*CH+h)*TT + t)*8 + d] = v;
        } else {
            int i = tid - 128; int h = i >> 3, d = i & 7;
            g_cv[((b*CH+h)*TT + t)*8 + d] = v;
        }
    }
}

// ---------------- K5: cross attention (d=8), 256 blocks ----------------
__global__ void __launch_bounds__(256) k5_crossattn(){
    int blk = blockIdx.x;              // 256 = (b,h) * 2 halves
    int c = blk >> 1;
    int t = (blk & 1)*256 + threadIdx.x;
    __shared__ float4 sK[TT*2];
    __shared__ float4 sV[TT*2];
    {
        const float4* kp = (const float4*)(g_ck + c*TT*8);
        const float4* vp = (const float4*)(g_cv + c*TT*8);
        for (int i = threadIdx.x; i < TT*2; i += 256){
            sK[i] = kp[i];
            sV[i] = vp[i];
        }
    }
    __syncthreads();
    float4 qa = ((const float4*)g_cq)[(c*TT + t)*2];
    float4 qb = ((const float4*)g_cq)[(c*TT + t)*2 + 1];
    float l0 = 0.f, l1 = 0.f;
    float o0[8], o1[8];
    #pragma unroll
    for (int j = 0; j < 8; j++){ o0[j] = 0.f; o1[j] = 0.f; }
    #pragma unroll 2
    for (int s = 0; s < TT; s += 2){
        float4 ka = sK[s*2],   kb = sK[s*2+1];
        float4 kc = sK[s*2+2], kd = sK[s*2+3];
        float sc0 = qa.x*ka.x;
        sc0 = fmaf(qa.y, ka.y, sc0); sc0 = fmaf(qa.z, ka.z, sc0); sc0 = fmaf(qa.w, ka.w, sc0);
        sc0 = fmaf(qb.x, kb.x, sc0); sc0 = fmaf(qb.y, kb.y, sc0);
        sc0 = fmaf(qb.z, kb.z, sc0); sc0 = fmaf(qb.w, kb.w, sc0);
        float sc1 = qa.x*kc.x;
        sc1 = fmaf(qa.y, kc.y, sc1); sc1 = fmaf(qa.z, kc.z, sc1); sc1 = fmaf(qa.w, kc.w, sc1);
        sc1 = fmaf(qb.x, kd.x, sc1); sc1 = fmaf(qb.y, kd.y, sc1);
        sc1 = fmaf(qb.z, kd.z, sc1); sc1 = fmaf(qb.w, kd.w, sc1);
        float p0 = __expf(sc0);
        float p1 = __expf(sc1);
        l0 += p0; l1 += p1;
        float4 va = sV[s*2],   vb = sV[s*2+1];
        float4 vc = sV[s*2+2], vd = sV[s*2+3];
        o0[0]=fmaf(p0,va.x,o0[0]); o0[1]=fmaf(p0,va.y,o0[1]); o0[2]=fmaf(p0,va.z,o0[2]); o0[3]=fmaf(p0,va.w,o0[3]);
        o0[4]=fmaf(p0,vb.x,o0[4]); o0[5]=fmaf(p0,vb.y,o0[5]); o0[6]=fmaf(p0,vb.z,o0[6]); o0[7]=fmaf(p0,vb.w,o0[7]);
        o1[0]=fmaf(p1,vc.x,o1[0]); o1[1]=fmaf(p1,vc.y,o1[1]); o1[2]=fmaf(p1,vc.z,o1[2]); o1[3]=fmaf(p1,vc.w,o1[3]);
        o1[4]=fmaf(p1,vd.x,o1[4]); o1[5]=fmaf(p1,vd.y,o1[5]); o1[6]=fmaf(p1,vd.z,o1[6]); o1[7]=fmaf(p1,vd.w,o1[7]);
    }
    float inv = __fdividef(1.f, l0 + l1);
    g_linv[c*TT + t] = inv;
    int b = c >> 3, h = c & 7;
    float* cop = g_co + (b*TT + t)*64 + h*8;
    #pragma unroll
    for (int j = 0; j < 8; j++) cop[j] = (o0[j]+o1[j])*inv;
}

// ---------------- K6: entropy by score recompute (no probs scratch) ----------------
__global__ void __launch_bounds__(128) k6_entropy(){
    int blk = blockIdx.x;              // 256 = b(16) * tile(4) * chunk(4)
    int b = blk >> 4;
    int tile = (blk >> 2) & 3;
    int chunk = blk & 3;
    int t = tile*128 + threadIdx.x;
    int s0 = chunk*128;
    __shared__ float4 sK[8*128*2];     // [h][s][2xfloat4] = 32KB
    for (int i = threadIdx.x; i < 2048; i += 128){
        int h = i >> 8, r = i & 255;
        sK[h*256 + r] = ((const float4*)g_ck)[ ((b*CH+h)*TT + s0)*2 + r ];
    }
    __syncthreads();
    float4 qa[8], qb[8];
    float invl[8];
    #pragma unroll
    for (int h = 0; h < 8; h++){
        qa[h] = ((const float4*)g_cq)[((b*CH+h)*TT + t)*2];
        qb[h] = ((const float4*)g_cq)[((b*CH+h)*TT + t)*2 + 1];
        invl[h] = g_linv[(b*CH+h)*TT + t] * 0.125f;
    }
    float acc = 0.f;
    for (int s = 0; s < 128; s++){
        float pm = 0.f;
        #pragma unroll
        for (int h = 0; h < 8; h++){
            float4 ka = sK[h*256 + s*2];
            float4 kb = sK[h*256 + s*2 + 1];
            float sc = qa[h].x*ka.x;
            sc = fmaf(qa[h].y, ka.y, sc); sc = fmaf(qa[h].z, ka.z, sc); sc = fmaf(qa[h].w, ka.w, sc);
            sc = fmaf(qb[h].x, kb.x, sc); sc = fmaf(qb[h].y, kb.y, sc);
            sc = fmaf(qb[h].z, kb.z, sc); sc = fmaf(qb[h].w, kb.w, sc);
            pm = fmaf(__expf(sc), invl[h], pm);
        }
        acc = fmaf(pm, __logf(pm + 1e-9f), acc);
    }
    g_entp[(b*TT + t)*4 + chunk] = acc;   // entropy = -sum of these
}

// ---------------- K7: fused epilogue, 8 tokens/block ----------------
__global__ void __launch_bounds__(256) k7_fused(
    const float* __restrict__ M, const int* __restrict__ token_ids,
    const float* __restrict__ cbout,
    const float* __restrict__ g1, const float* __restrict__ be1,
    const float* __restrict__ fb1,
    const float* __restrict__ fb2,
    const float* __restrict__ g2, const float* __restrict__ be2,
    const float* __restrict__ sbase, const float* __restrict__ taff,
    const float* __restrict__ sw1, const float* __restrict__ sb1,
    const float* __restrict__ sw2, const float* __restrict__ sb2,
    float* __restrict__ out)
{
    int bt0 = blockIdx.x * 8;
    int tid = threadIdx.x;
    int lane = tid & 31, warp = tid >> 5;

    __shared__ float s_coT[64*8];     // [o][tok]
    __shared__ float s_abT[64*8];
    __shared__ float s_yT [64*8];
    __shared__ float s_xT [64*8];
    __shared__ float s_x2T[64*8];
    __shared__ float s_h1T[256*8];    // [o][tok]
    __shared__ float s_fp [4*64*8];   // partials [qr][o][tok]
    __shared__ float s_mu[8], s_rs[8];
    __shared__ float s_ent[8];
    __shared__ float s_hs[8*32];
    __shared__ float s_sens[8*16];

    // A: load co and ab (coalesced), transpose to [o][tok]
    for (int idx = tid; idx < 512; idx += 256){
        int tok = idx >> 6, o = idx & 63;
        s_coT[o*8 + tok] = g_co[(bt0+tok)*64 + o];
        s_abT[o*8 + tok] = g_ab[(bt0+tok)*64 + o];
    }
    __syncthreads();

    int o64 = tid & 63, qr = tid >> 6;

    // B: cross out-proj GEMM (split j 4-ways)
    {
        float acc[8];
        #pragma unroll
        for (int k = 0; k < 8; k++) acc[k] = 0.f;
        int j0 = qr*16;
        #pragma unroll
        for (int j = j0; j < j0+16; j++){
            float w = g_cwoutT[j*64 + o64];
            float4 c0 = *(const float4*)&s_coT[j*8];
            float4 c1 = *(const float4*)&s_coT[j*8 + 4];
            acc[0]=fmaf(w,c0.x,acc[0]); acc[1]=fmaf(w,c0.y,acc[1]);
            acc[2]=fmaf(w,c0.z,acc[2]); acc[3]=fmaf(w,c0.w,acc[3]);
            acc[4]=fmaf(w,c1.x,acc[4]); acc[5]=fmaf(w,c1.y,acc[5]);
            acc[6]=fmaf(w,c1.z,acc[6]); acc[7]=fmaf(w,c1.w,acc[7]);
        }
        #pragma unroll
        for (int k = 0; k < 8; k++) s_fp[qr*512 + o64*8 + k] = acc[k];
    }
    __syncthreads();
    for (int idx = tid; idx < 512; idx += 256){
        int o = idx >> 3, tok = idx & 7;
        float y = cbout[o] + s_abT[o*8+tok]
                + s_fp[o*8+tok] + s_fp[512 + o*8+tok]
                + s_fp[1024 + o*8+tok] + s_fp[1536 + o*8+tok];
        s_yT[o*8 + tok] = y;
    }
    __syncthreads();

    // C: LN1 stats (warp w handles token w)
    {
        float v0 = s_yT[lane*8 + warp];
        float v1 = s_yT[(lane+32)*8 + warp];
        float sv = v0 + v1, sq = v0*v0 + v1*v1;
        #pragma unroll
        for (int off = 16; off > 0; off >>= 1){
            sv += __shfl_down_sync(0xffffffffu, sv, off);
            sq += __shfl_down_sync(0xffffffffu, sq, off);
        }
        if (lane == 0){
            float mean = sv * (1.f/64.f);
            float var  = sq * (1.f/64.f) - mean*mean;
            s_mu[warp] = mean;
            s_rs[warp] = rsqrtf(var + 1e-5f);
        }
    }
    __syncthreads();

    // D: LN1 apply
    for (int idx = tid; idx < 512; idx += 256){
        int o = idx >> 3, tok = idx & 7;
        s_xT[o*8+tok] = (s_yT[o*8+tok] - s_mu[tok]) * s_rs[tok] * g1[o] + be1[o];
    }
    __syncthreads();

    // E: FFN1 (each thread one of 256 outputs, 8 tokens)
    {
        float acc[8];
        float bs = fb1[tid];
        #pragma unroll
        for (int k = 0; k < 8; k++) acc[k] = bs;
        #pragma unroll 8
        for (int j = 0; j < 64; j++){
            float w = g_fw1T[j*256 + tid];
            float4 x0 = *(const float4*)&s_xT[j*8];
            float4 x1 = *(const float4*)&s_xT[j*8 + 4];
            acc[0]=fmaf(w,x0.x,acc[0]); acc[1]=fmaf(w,x0.y,acc[1]);
            acc[2]=fmaf(w,x0.z,acc[2]); acc[3]=fmaf(w,x0.w,acc[3]);
            acc[4]=fmaf(w,x1.x,acc[4]); acc[5]=fmaf(w,x1.y,acc[5]);
            acc[6]=fmaf(w,x1.z,acc[6]); acc[7]=fmaf(w,x1.w,acc[7]);
        }
        #pragma unroll
        for (int k = 0; k < 8; k++) s_h1T[tid*8 + k] = gelu_f(acc[k]);
    }
    __syncthreads();

    // F: FFN2 (split j 4-ways)
    {
        float acc[8];
        #pragma unroll
        for (int k = 0; k < 8; k++) acc[k] = 0.f;
        int j0 = qr*64;
        #pragma unroll 8
        for (int j = j0; j < j0+64; j++){
            float w = g_fw2T[j*64 + o64];
            float4 h0 = *(const float4*)&s_h1T[j*8];
            float4 h1 = *(const float4*)&s_h1T[j*8 + 4];
            acc[0]=fmaf(w,h0.x,acc[0]); acc[1]=fmaf(w,h0.y,acc[1]);
            acc[2]=fmaf(w,h0.z,acc[2]); acc[3]=fmaf(w,h0.w,acc[3]);
            acc[4]=fmaf(w,h1.x,acc[4]); acc[5]=fmaf(w,h1.y,acc[5]);
            acc[6]=fmaf(w,h1.z,acc[6]); acc[7]=fmaf(w,h1.w,acc[7]);
        }
        #pragma unroll
        for (int k = 0; k < 8; k++) s_fp[qr*512 + o64*8 + k] = acc[k];
    }
    __syncthreads();
    for (int idx = tid; idx < 512; idx += 256){
        int o = idx >> 3, tok = idx & 7;
        float z = s_xT[o*8+tok] + fb2[o]
                + s_fp[o*8+tok] + s_fp[512 + o*8+tok]
                + s_fp[1024 + o*8+tok] + s_fp[1536 + o*8+tok];
        s_yT[o*8 + tok] = z;
    }
    __syncthreads();

    // LN2 stats
    {
        float v0 = s_yT[lane*8 + warp];
        float v1 = s_yT[(lane+32)*8 + warp];
        float sv = v0 + v1, sq = v0*v0 + v1*v1;
        #pragma unroll
        for (int off = 16; off > 0; off >>= 1){
            sv += __shfl_down_sync(0xffffffffu, sv, off);
            sq += __shfl_down_sync(0xffffffffu, sq, off);
        }
        if (lane == 0){
            float mean = sv * (1.f/64.f);
            float var  = sq * (1.f/64.f) - mean*mean;
            s_mu[warp] = mean;
            s_rs[warp] = rsqrtf(var + 1e-5f);
        }
    }
    __syncthreads();
    for (int idx = tid; idx < 512; idx += 256){
        int o = idx >> 3, tok = idx & 7;
        s_x2T[o*8+tok] = (s_yT[o*8+tok] - s_mu[tok]) * s_rs[tok] * g2[o] + be2[o];
    }
    if (tid < 8){
        float e = 0.f;
        #pragma unroll
        for (int c = 0; c < 4; c++) e += g_entp[(bt0+tid)*4 + c];
        s_ent[tid] = -e;
    }
    __syncthreads();

    // H: sensitivity MLP (8 toks x 32 hidden)
    {
        int tok = tid >> 5, hh = tid & 31;
        int tk = token_ids[bt0 + tok];
        float acc = sb1[hh];
        const float* wp = sw1 + hh*17;
        const float* ap = taff + (size_t)tk*16;
        #pragma unroll
        for (int a = 0; a < 16; a++) acc = fmaf(wp[a], ap[a], acc);
        acc = fmaf(wp[16], s_ent[tok], acc);
        s_hs[tok*32 + hh] = gelu_f(acc);
    }
    __syncthreads();
    if (tid < 128){
        int tok = tid >> 4, oo = tid & 15;
        float acc = sb2[oo];
        const float* wp = sw2 + oo*32;
        #pragma unroll
        for (int j = 0; j < 32; j++) acc = fmaf(wp[j], s_hs[tok*32 + j], acc);
        s_sens[tok*16 + oo] = sbase[oo] / (1.f + __expf(-acc));
    }
    __syncthreads();

    // I: gated update (coalesced)
    for (int idx = tid; idx < 512; idx += 256){
        int tok = idx >> 6, o = idx & 63;
        float m = M[(bt0+tok)*64 + o];
        out[(bt0+tok)*64 + o] = fmaf(s_x2T[o*8+tok] - m, s_sens[tok*16 + (o>>2)], m);
    }
}

// ---------------- launch ----------------
extern "C" void kernel_launch(void* const* d_in, const int* in_sizes, int n_in,
                              void* d_out, int out_size){
    const float* M     = (const float*)d_in[0];
    const int*   tok   = (const int*)  d_in[1];
    const float* bwqkv = (const float*)d_in[2];
    const float* bbqkv = (const float*)d_in[3];
    const float* bwout = (const float*)d_in[4];
    const float* bbout = (const float*)d_in[5];
    const float* cwqkv = (const float*)d_in[6];
    const float* cbqkv = (const float*)d_in[7];
    const float* cwout = (const float*)d_in[8];
    const float* cbout = (const float*)d_in[9];
    const float* g1    = (const float*)d_in[10];
    const float* b1    = (const float*)d_in[11];
    const float* fw1   = (const float*)d_in[12];
    const float* fb1   = (const float*)d_in[13];
    const float* fw2   = (const float*)d_in[14];
    const float* fb2   = (const float*)d_in[15];
    const float* g2    = (const float*)d_in[16];
    const float* b2    = (const float*)d_in[17];
    const float* sbase = (const float*)d_in[18];
    const float* taff  = (const float*)d_in[19];
    const float* sw1   = (const float*)d_in[20];
    const float* sb1   = (const float*)d_in[21];
    const float* sw2   = (const float*)d_in[22];
    const float* sb2   = (const float*)d_in[23];

    k0_transpose<<<48, 256>>>(cwqkv, cwout, fw1, fw2);
    k1_blockqkv<<<BB*TT, 192>>>(M, bwqkv, bbqkv);
    k2_blockattn<<<BB*NB*2, TT>>>();
    k4_crossqkv<<<BB*TT/8, 192>>>(bwout, bbout, cbqkv);
    k5_crossattn<<<BB*CH*2, 256>>>();
    k6_entropy<<<256, 128>>>();
    k7_fused<<<BB*TT/8, 256>>>(M, tok, cbout, g1, b1, fb1, fb2, g2, b2,
                               sbase, taff, sw1, sb1, sw2, sb2, (float*)d_out);
}

// round 5
// speedup vs baseline: 8.7846x; 1.1850x over previous
#include <cuda_runtime.h>
#include <cstdint>

#define BB 16
#define TT 512
#define NB 16
#define CH 8

typedef unsigned long long ull;

// ---------------- packed f32x2 helpers ----------------
__device__ __forceinline__ ull pk2(float a, float b){
    ull r; asm("mov.b64 %0, {%1,%2};" : "=l"(r) : "f"(a), "f"(b)); return r; }
__device__ __forceinline__ void upk2(ull v, float& a, float& b){
    asm("mov.b64 {%0,%1}, %2;" : "=f"(a), "=f"(b) : "l"(v)); }
__device__ __forceinline__ void fma2(ull& d, ull a, ull b){
    asm("fma.rn.f32x2 %0, %1, %2, %0;" : "+l"(d) : "l"(a), "l"(b)); }
__device__ __forceinline__ ull mul2(ull a, ull b){
    ull r; asm("mul.rn.f32x2 %0, %1, %2;" : "=l"(r) : "l"(a), "l"(b)); return r; }
__device__ __forceinline__ void add2(ull& d, ull a){
    asm("add.rn.f32x2 %0, %0, %1;" : "+l"(d) : "l"(a)); }
__device__ __forceinline__ float ex2f(float x){
    float r; asm("ex2.approx.f32 %0, %1;" : "=f"(r) : "f"(x)); return r; }

#define QS  (0.70710678118654752f * 1.4426950408889634f)
#define CS  (0.35355339059327376f * 1.4426950408889634f)

// ---------------- scratch ----------------
__device__ __align__(16) float g_q  [BB*NB*2*TT*2];   // [c][t][2], prescaled QS
__device__ __align__(16) float g_kv [BB*NB*2*TT*4];   // [c][pair][kx0,kx1,ky0,ky1,vz0,vz1,vw0,vw1]
__device__ __align__(16) float g_o  [BB*TT*64];       // token-major block attn out
__device__ __align__(16) float g_ab [BB*TT*64];
__device__ __align__(16) float g_cq [BB*CH*TT*8];     // [c2][t][8], prescaled CS
__device__ __align__(16) float g_ck [BB*CH*TT*8];     // [c2][pair][dim(8)][2]
__device__ __align__(16) float g_cv [BB*CH*TT*8];     // same paired layout
__device__ __align__(16) float g_co [BB*TT*64];
__device__ __align__(16) float g_linv[BB*CH*TT];
__device__ __align__(16) float g_entp[BB*TT*16];      // 16 s-chunks of 32

__device__ __align__(16) float g_cwqkvT[64*192];
__device__ __align__(16) float g_cwoutT[64*64];
__device__ __align__(16) float g_fw1T[64*256];
__device__ __align__(16) float g_fw2T[256*64];

__device__ __forceinline__ float gelu_f(float x){
    return 0.5f * x * (1.0f + erff(x * 0.70710678118654752f));
}

// ---------------- K0: transpose weights ----------------
__global__ void k0_transpose(const float* __restrict__ cwqkv,
                             const float* __restrict__ cwout,
                             const float* __restrict__ fw1,
                             const float* __restrict__ fw2){
    int stride = gridDim.x * blockDim.x;
    int tid0 = blockIdx.x * blockDim.x + threadIdx.x;
    for (int idx = tid0; idx < 64*192; idx += stride){
        int j = idx / 192, o = idx - j*192;
        g_cwqkvT[idx] = cwqkv[o*64 + j];
    }
    for (int idx = tid0; idx < 64*64; idx += stride){
        int j = idx >> 6, o = idx & 63;
        g_cwoutT[idx] = cwout[o*64 + j];
    }
    for (int idx = tid0; idx < 64*256; idx += stride){
        int j = idx >> 8, o = idx & 255;
        g_fw1T[idx] = fw1[o*64 + j];
    }
    for (int idx = tid0; idx < 256*64; idx += stride){
        int j = idx >> 6, o = idx & 63;
        g_fw2T[idx] = fw2[o*256 + j];
    }
}

// ---------------- K1: block extraction + tiny QKV (4 tok/block) ----------------
__global__ void __launch_bounds__(256) k1_blockqkv(const float* __restrict__ M,
                            const float* __restrict__ w,
                            const float* __restrict__ bias){
    int bt0 = blockIdx.x * 4;
    int b = bt0 >> 9;
    __shared__ float mrow[256];
    int tid = threadIdx.x;
    mrow[tid] = M[bt0*64 + tid];
    __syncthreads();
    #pragma unroll
    for (int it = 0; it < 3; it++){
        int idx = tid + it*256;            // < 768 = 4 tok * 192
        int tok = idx / 192, r = idx - tok*192;
        int t = (bt0 + tok) & 511;
        int n = r / 12, e = r - n*12;
        int br = n >> 2, bc = n & 3;
        int base = tok*64 + 16*br + 2*bc;
        float x0 = mrow[base], x1 = mrow[base+1], x2 = mrow[base+8], x3 = mrow[base+9];
        const float* wp = w + r*4;
        float val = bias[r] + wp[0]*x0 + wp[1]*x1 + wp[2]*x2 + wp[3]*x3;
        if (e < 4){
            int h = e >> 1, d = e & 1;
            g_q[(((b*NB+n)*2+h)*TT + t)*2 + d] = val * QS;
        } else if (e < 8){
            int ee = e - 4; int h = ee >> 1, d = ee & 1;   // comp = d
            g_kv[((b*NB+n)*2+h)*TT*4 + (t>>1)*8 + d*2 + (t&1)] = val;
        } else {
            int ee = e - 8; int h = ee >> 1, d = ee & 1;   // comp = 2+d
            g_kv[((b*NB+n)*2+h)*TT*4 + (t>>1)*8 + 4 + d*2 + (t&1)] = val;
        }
    }
}

// ---------------- K2: 512 tiny attentions (d=2), paired ----------------
__global__ void __launch_bounds__(TT) k2_blockattn(){
    int c = blockIdx.x;                // 512
    __shared__ __align__(16) float sKV[TT*4];
    int t = threadIdx.x;
    ((float4*)sKV)[t] = ((const float4*)g_kv)[c*TT + t];   // 512 float4 = 2048 floats
    __syncthreads();
    float2 q = ((const float2*)g_q)[c*TT + t];
    ull qxx = pk2(q.x, q.x), qyy = pk2(q.y, q.y);
    ull l2 = 0ull, oz2 = 0ull, ow2 = 0ull;
    const ulonglong2* s2 = (const ulonglong2*)sKV;
    #pragma unroll 8
    for (int p = 0; p < 256; p++){
        ulonglong2 kk = s2[p*2];
        ulonglong2 vv = s2[p*2+1];
        ull sc2 = mul2(qxx, kk.x);
        fma2(sc2, qyy, kk.y);
        float s0, s1; upk2(sc2, s0, s1);
        ull pp = pk2(ex2f(s0), ex2f(s1));
        add2(l2, pp);
        fma2(oz2, pp, vv.x);
        fma2(ow2, pp, vv.y);
    }
    float la, lb, za, zb, wa, wb;
    upk2(l2, la, lb); upk2(oz2, za, zb); upk2(ow2, wa, wb);
    float inv = __fdividef(1.f, la + lb);
    int b = c >> 5, n = (c >> 1) & 15, h = c & 1;
    ((float2*)g_o)[(b*TT + t)*32 + n*2 + h] = make_float2((za+zb)*inv, (wa+wb)*inv);
}

// ---------------- K4: block out-proj + cross QKV, 8 tok/block, packed ----------------
__global__ void __launch_bounds__(192) k4_crossqkv(const float* __restrict__ bw,
                                                   const float* __restrict__ bb,
                                                   const float* __restrict__ bias){
    int bt0 = blockIdx.x * 8;
    int b = bt0 >> 9;
    int tid = threadIdx.x;
    __shared__ __align__(16) float s_xT[64*8];     // [o][tok]

    for (int idx = tid; idx < 512; idx += 192){
        int tok = idx >> 6, o = idx & 63;
        int n = o >> 2;
        float4 ov = ((const float4*)g_o)[(bt0+tok)*16 + n];
        float4 wv = ((const float4*)bw)[o];
        float acc = bb[o];
        acc = fmaf(wv.x, ov.x, acc); acc = fmaf(wv.y, ov.y, acc);
        acc = fmaf(wv.z, ov.z, acc); acc = fmaf(wv.w, ov.w, acc);
        s_xT[o*8 + tok] = acc;
        g_ab[(bt0+tok)*64 + o] = acc;
    }
    __syncthreads();

    float bs = bias[tid];
    ull acc[4];
    #pragma unroll
    for (int k = 0; k < 4; k++) acc[k] = pk2(bs, bs);
    #pragma unroll 8
    for (int j = 0; j < 64; j++){
        float w = g_cwqkvT[j*192 + tid];
        ull ww = pk2(w, w);
        const ull* xp = (const ull*)&s_xT[j*8];
        fma2(acc[0], ww, xp[0]); fma2(acc[1], ww, xp[1]);
        fma2(acc[2], ww, xp[2]); fma2(acc[3], ww, xp[3]);
    }
    float av[8];
    upk2(acc[0], av[0], av[1]); upk2(acc[1], av[2], av[3]);
    upk2(acc[2], av[4], av[5]); upk2(acc[3], av[6], av[7]);
    #pragma unroll
    for (int tok = 0; tok < 8; tok++){
        int t = (bt0 + tok) & 511;
        float v = av[tok];
        if (tid < 64){
            int h = tid >> 3, d = tid & 7;
            g_cq[((b*CH+h)*TT + t)*8 + d] = v * CS;
        } else if (tid < 128){
            int i = tid - 64; int h = i >> 3, d = i & 7;
            g_ck[(b*CH+h)*TT*8 + (t>>1)*16 + d*2 + (t&1)] = v;
        } else {
            int i = tid - 128; int h = i >> 3, d = i & 7;
            g_cv[(b*CH+h)*TT*8 + (t>>1)*16 + d*2 + (t&1)] = v;
        }
    }
}

// ---------------- K5: cross attention (d=8), paired, 512 blocks ----------------
__global__ void __launch_bounds__(128) k5_crossattn(){
    int blk = blockIdx.x;              // 512 = c2(128) * quarter(4)
    int c = blk >> 2;
    int t = (blk & 3)*128 + threadIdx.x;
    __shared__ __align__(16) float sK[TT*8];
    __shared__ __align__(16) float sV[TT*8];
    {
        const float4* kp = (const float4*)(g_ck + c*TT*8);
        const float4* vp = (const float4*)(g_cv + c*TT*8);
        for (int i = threadIdx.x; i < 1024; i += 128){
            ((float4*)sK)[i] = kp[i];
            ((float4*)sV)[i] = vp[i];
        }
    }
    __syncthreads();
    ull qjj[8];
    {
        float4 qa = ((const float4*)g_cq)[(c*TT + t)*2];
        float4 qb = ((const float4*)g_cq)[(c*TT + t)*2 + 1];
        qjj[0]=pk2(qa.x,qa.x); qjj[1]=pk2(qa.y,qa.y); qjj[2]=pk2(qa.z,qa.z); qjj[3]=pk2(qa.w,qa.w);
        qjj[4]=pk2(qb.x,qb.x); qjj[5]=pk2(qb.y,qb.y); qjj[6]=pk2(qb.z,qb.z); qjj[7]=pk2(qb.w,qb.w);
    }
    ull l2 = 0ull;
    ull o2[8];
    #pragma unroll
    for (int j = 0; j < 8; j++) o2[j] = 0ull;
    const ulonglong2* kp2 = (const ulonglong2*)sK;
    const ulonglong2* vp2 = (const ulonglong2*)sV;
    #pragma unroll 2
    for (int p = 0; p < 256; p++){
        ulonglong2 k0 = kp2[p*4], k1 = kp2[p*4+1], k2v = kp2[p*4+2], k3 = kp2[p*4+3];
        ull sc2 = mul2(qjj[0], k0.x);
        fma2(sc2, qjj[1], k0.y); fma2(sc2, qjj[2], k1.x); fma2(sc2, qjj[3], k1.y);
        fma2(sc2, qjj[4], k2v.x); fma2(sc2, qjj[5], k2v.y);
        fma2(sc2, qjj[6], k3.x); fma2(sc2, qjj[7], k3.y);
        float s0, s1; upk2(sc2, s0, s1);
        ull pp = pk2(ex2f(s0), ex2f(s1));
        add2(l2, pp);
        ulonglong2 v0 = vp2[p*4], v1 = vp2[p*4+1], v2v = vp2[p*4+2], v3 = vp2[p*4+3];
        fma2(o2[0], pp, v0.x); fma2(o2[1], pp, v0.y);
        fma2(o2[2], pp, v1.x); fma2(o2[3], pp, v1.y);
        fma2(o2[4], pp, v2v.x); fma2(o2[5], pp, v2v.y);
        fma2(o2[6], pp, v3.x); fma2(o2[7], pp, v3.y);
    }
    float la, lb; upk2(l2, la, lb);
    float inv = __fdividef(1.f, la + lb);
    g_linv[c*TT + t] = inv;
    int b = c >> 3, h = c & 7;
    float* cop = g_co + (b*TT + t)*64 + h*8;
    #pragma unroll
    for (int j = 0; j < 8; j++){
        float oa, ob; upk2(o2[j], oa, ob);
        cop[j] = (oa + ob) * inv;
    }
}

// ---------------- K6: entropy by recompute, paired, h-outer ----------------
__global__ void __launch_bounds__(128) k6_entropy(){
    int blk = blockIdx.x;              // 1024 = b(16) * tile(4) * chunk(16)
    int b = blk >> 6;
    int tile = (blk >> 4) & 3;
    int chunk = blk & 15;              // 32 s per chunk = 16 pairs
    int t = tile*128 + threadIdx.x;
    __shared__ __align__(16) float sK[8*256];   // 8 heads x 16 pairs x 16 floats
    for (int i = threadIdx.x; i < 512; i += 128){
        int h = i >> 6, f = i & 63;
        ((float4*)sK)[i] = ((const float4*)g_ck)[(b*CH+h)*1024 + chunk*64 + f];
    }
    __syncthreads();
    ull pm2[16];
    #pragma unroll
    for (int p = 0; p < 16; p++) pm2[p] = 0ull;
    #pragma unroll
    for (int h = 0; h < 8; h++){
        float4 qa = ((const float4*)g_cq)[((b*CH+h)*TT + t)*2];
        float4 qb = ((const float4*)g_cq)[((b*CH+h)*TT + t)*2 + 1];
        ull q0=pk2(qa.x,qa.x), q1=pk2(qa.y,qa.y), q2=pk2(qa.z,qa.z), q3=pk2(qa.w,qa.w);
        ull q4=pk2(qb.x,qb.x), q5=pk2(qb.y,qb.y), q6=pk2(qb.z,qb.z), q7=pk2(qb.w,qb.w);
        float il = g_linv[(b*CH+h)*TT + t] * 0.125f;
        ull ivv = pk2(il, il);
        const ulonglong2* kh = (const ulonglong2*)(sK + h*256);
        #pragma unroll
        for (int p = 0; p < 16; p++){
            ulonglong2 k0 = kh[p*4], k1 = kh[p*4+1], k2v = kh[p*4+2], k3 = kh[p*4+3];
            ull sc2 = mul2(q0, k0.x);
            fma2(sc2, q1, k0.y); fma2(sc2, q2, k1.x); fma2(sc2, q3, k1.y);
            fma2(sc2, q4, k2v.x); fma2(sc2, q5, k2v.y);
            fma2(sc2, q6, k3.x); fma2(sc2, q7, k3.y);
            float s0, s1; upk2(sc2, s0, s1);
            ull pp = pk2(ex2f(s0), ex2f(s1));
            fma2(pm2[p], pp, ivv);
        }
    }
    float acc = 0.f;
    #pragma unroll
    for (int p = 0; p < 16; p++){
        float m0, m1; upk2(pm2[p], m0, m1);
        acc = fmaf(m0, __logf(m0 + 1e-9f), acc);
        acc = fmaf(m1, __logf(m1 + 1e-9f), acc);
    }
    g_entp[(b*TT + t)*16 + chunk] = acc;   // entropy = -sum
}

// ---------------- K7: fused epilogue, 8 tok/block, packed GEMMs ----------------
__global__ void __launch_bounds__(256) k7_fused(
    const float* __restrict__ M, const int* __restrict__ token_ids,
    const float* __restrict__ cbout,
    const float* __restrict__ g1, const float* __restrict__ be1,
    const float* __restrict__ fb1,
    const float* __restrict__ fb2,
    const float* __restrict__ g2, const float* __restrict__ be2,
    const float* __restrict__ sbase, const float* __restrict__ taff,
    const float* __restrict__ sw1, const float* __restrict__ sb1,
    const float* __restrict__ sw2, const float* __restrict__ sb2,
    float* __restrict__ out)
{
    int bt0 = blockIdx.x * 8;
    int tid = threadIdx.x;
    int lane = tid & 31, warp = tid >> 5;

    __shared__ __align__(16) float s_coT[64*8];
    __shared__ __align__(16) float s_abT[64*8];
    __shared__ __align__(16) float s_yT [64*8];
    __shared__ __align__(16) float s_xT [64*8];
    __shared__ __align__(16) float s_x2T[64*8];
    __shared__ __align__(16) float s_h1T[256*8];
    __shared__ __align__(16) float s_fp [4*64*8];
    __shared__ float s_mu[8], s_rs[8];
    __shared__ float s_ent[8];
    __shared__ float s_hs[8*32];
    __shared__ float s_sens[8*16];

    for (int idx = tid; idx < 512; idx += 256){
        int tok = idx >> 6, o = idx & 63;
        s_coT[o*8 + tok] = g_co[(bt0+tok)*64 + o];
        s_abT[o*8 + tok] = g_ab[(bt0+tok)*64 + o];
    }
    __syncthreads();

    int o64 = tid & 63, qr = tid >> 6;

    // B: cross out-proj (j split 4-ways, packed)
    {
        ull acc[4] = {0ull, 0ull, 0ull, 0ull};
        int j0 = qr*16;
        #pragma unroll
        for (int j = j0; j < j0+16; j++){
            float w = g_cwoutT[j*64 + o64];
            ull ww = pk2(w, w);
            const ull* cp = (const ull*)&s_coT[j*8];
            fma2(acc[0], ww, cp[0]); fma2(acc[1], ww, cp[1]);
            fma2(acc[2], ww, cp[2]); fma2(acc[3], ww, cp[3]);
        }
        ull* fp = (ull*)&s_fp[qr*512 + o64*8];
        fp[0]=acc[0]; fp[1]=acc[1]; fp[2]=acc[2]; fp[3]=acc[3];
    }
    __syncthreads();
    for (int idx = tid; idx < 512; idx += 256){
        int o = idx >> 3, tok = idx & 7;
        s_yT[o*8 + tok] = cbout[o] + s_abT[o*8+tok]
                + s_fp[o*8+tok] + s_fp[512 + o*8+tok]
                + s_fp[1024 + o*8+tok] + s_fp[1536 + o*8+tok];
    }
    __syncthreads();

    // LN1 stats
    {
        float v0 = s_yT[lane*8 + warp];
        float v1 = s_yT[(lane+32)*8 + warp];
        float sv = v0 + v1, sq = v0*v0 + v1*v1;
        #pragma unroll
        for (int off = 16; off > 0; off >>= 1){
            sv += __shfl_down_sync(0xffffffffu, sv, off);
            sq += __shfl_down_sync(0xffffffffu, sq, off);
        }
        if (lane == 0){
            float mean = sv * (1.f/64.f);
            float var  = sq * (1.f/64.f) - mean*mean;
            s_mu[warp] = mean;
            s_rs[warp] = rsqrtf(var + 1e-5f);
        }
    }
    __syncthreads();
    for (int idx = tid; idx < 512; idx += 256){
        int o = idx >> 3, tok = idx & 7;
        s_xT[o*8+tok] = (s_yT[o*8+tok] - s_mu[tok]) * s_rs[tok] * g1[o] + be1[o];
    }
    __syncthreads();

    // FFN1 (packed)
    {
        float bs = fb1[tid];
        ull acc[4];
        #pragma unroll
        for (int k = 0; k < 4; k++) acc[k] = pk2(bs, bs);
        #pragma unroll 8
        for (int j = 0; j < 64; j++){
            float w = g_fw1T[j*256 + tid];
            ull ww = pk2(w, w);
            const ull* xp = (const ull*)&s_xT[j*8];
            fma2(acc[0], ww, xp[0]); fma2(acc[1], ww, xp[1]);
            fma2(acc[2], ww, xp[2]); fma2(acc[3], ww, xp[3]);
        }
        ull* hp = (ull*)&s_h1T[tid*8];
        #pragma unroll
        for (int k = 0; k < 4; k++){
            float a, bvl; upk2(acc[k], a, bvl);
            hp[k] = pk2(gelu_f(a), gelu_f(bvl));
        }
    }
    __syncthreads();

    // FFN2 (j split 4-ways, packed)
    {
        ull acc[4] = {0ull, 0ull, 0ull, 0ull};
        int j0 = qr*64;
        #pragma unroll 8
        for (int j = j0; j < j0+64; j++){
            float w = g_fw2T[j*64 + o64];
            ull ww = pk2(w, w);
            const ull* hp = (const ull*)&s_h1T[j*8];
            fma2(acc[0], ww, hp[0]); fma2(acc[1], ww, hp[1]);
            fma2(acc[2], ww, hp[2]); fma2(acc[3], ww, hp[3]);
        }
        ull* fp = (ull*)&s_fp[qr*512 + o64*8];
        fp[0]=acc[0]; fp[1]=acc[1]; fp[2]=acc[2]; fp[3]=acc[3];
    }
    __syncthreads();
    for (int idx = tid; idx < 512; idx += 256){
        int o = idx >> 3, tok = idx & 7;
        s_yT[o*8 + tok] = s_xT[o*8+tok] + fb2[o]
                + s_fp[o*8+tok] + s_fp[512 + o*8+tok]
                + s_fp[1024 + o*8+tok] + s_fp[1536 + o*8+tok];
    }
    __syncthreads();

    // LN2 stats
    {
        float v0 = s_yT[lane*8 + warp];
        float v1 = s_yT[(lane+32)*8 + warp];
        float sv = v0 + v1, sq = v0*v0 + v1*v1;
        #pragma unroll
        for (int off = 16; off > 0; off >>= 1){
            sv += __shfl_down_sync(0xffffffffu, sv, off);
            sq += __shfl_down_sync(0xffffffffu, sq, off);
        }
        if (lane == 0){
            float mean = sv * (1.f/64.f);
            float var  = sq * (1.f/64.f) - mean*mean;
            s_mu[warp] = mean;
            s_rs[warp] = rsqrtf(var + 1e-5f);
        }
    }
    __syncthreads();
    for (int idx = tid; idx < 512; idx += 256){
        int o = idx >> 3, tok = idx & 7;
        s_x2T[o*8+tok] = (s_yT[o*8+tok] - s_mu[tok]) * s_rs[tok] * g2[o] + be2[o];
    }
    if (tid < 8){
        float e = 0.f;
        #pragma unroll
        for (int c = 0; c < 16; c++) e += g_entp[(bt0+tid)*16 + c];
        s_ent[tid] = -e;
    }
    __syncthreads();

    // sensitivity MLP
    {
        int tok = tid >> 5, hh = tid & 31;
        int tk = token_ids[bt0 + tok];
        float acc = sb1[hh];
        const float* wp = sw1 + hh*17;
        const float* ap = taff + (size_t)tk*16;
        #pragma unroll
        for (int a = 0; a < 16; a++) acc = fmaf(wp[a], ap[a], acc);
        acc = fmaf(wp[16], s_ent[tok], acc);
        s_hs[tok*32 + hh] = gelu_f(acc);
    }
    __syncthreads();
    if (tid < 128){
        int tok = tid >> 4, oo = tid & 15;
        float acc = sb2[oo];
        const float* wp = sw2 + oo*32;
        #pragma unroll
        for (int j = 0; j < 32; j++) acc = fmaf(wp[j], s_hs[tok*32 + j], acc);
        s_sens[tok*16 + oo] = sbase[oo] / (1.f + __expf(-acc));
    }
    __syncthreads();

    for (int idx = tid; idx < 512; idx += 256){
        int tok = idx >> 6, o = idx & 63;
        float m = M[(bt0+tok)*64 + o];
        out[(bt0+tok)*64 + o] = fmaf(s_x2T[o*8+tok] - m, s_sens[tok*16 + (o>>2)], m);
    }
}

// ---------------- launch ----------------
extern "C" void kernel_launch(void* const* d_in, const int* in_sizes, int n_in,
                              void* d_out, int out_size){
    const float* M     = (const float*)d_in[0];
    const int*   tok   = (const int*)  d_in[1];
    const float* bwqkv = (const float*)d_in[2];
    const float* bbqkv = (const float*)d_in[3];
    const float* bwout = (const float*)d_in[4];
    const float* bbout = (const float*)d_in[5];
    const float* cwqkv = (const float*)d_in[6];
    const float* cbqkv = (const float*)d_in[7];
    const float* cwout = (const float*)d_in[8];
    const float* cbout = (const float*)d_in[9];
    const float* g1    = (const float*)d_in[10];
    const float* b1    = (const float*)d_in[11];
    const float* fw1   = (const float*)d_in[12];
    const float* fb1   = (const float*)d_in[13];
    const float* fw2   = (const float*)d_in[14];
    const float* fb2   = (const float*)d_in[15];
    const float* g2    = (const float*)d_in[16];
    const float* b2    = (const float*)d_in[17];
    const float* sbase = (const float*)d_in[18];
    const float* taff  = (const float*)d_in[19];
    const float* sw1   = (const float*)d_in[20];
    const float* sb1   = (const float*)d_in[21];
    const float* sw2   = (const float*)d_in[22];
    const float* sb2   = (const float*)d_in[23];

    k0_transpose<<<48, 256>>>(cwqkv, cwout, fw1, fw2);
    k1_blockqkv<<<BB*TT/4, 256>>>(M, bwqkv, bbqkv);
    k2_blockattn<<<BB*NB*2, TT>>>();
    k4_crossqkv<<<BB*TT/8, 192>>>(bwout, bbout, cbqkv);
    k5_crossattn<<<BB*CH*4, 128>>>();
    k6_entropy<<<1024, 128>>>();
    k7_fused<<<BB*TT/8, 256>>>(M, tok, cbout, g1, b1, fb1, fb2, g2, b2,
                               sbase, taff, sw1, sb1, sw2, sb2, (float*)d_out);
}